// round 1
// baseline (speedup 1.0000x reference)
#include <cuda_runtime.h>
#include <math.h>

#define Bz   8
#define Cc   512
#define Nn   4096
#define Mm   64
#define Rr   640        // Mm + Mm + Cc
#define EPSc 1e-6f

// ---------------- device scratch (no allocations allowed) ----------------
__device__ float g_Qf[Bz*Mm*Nn];   // softplus(Q)  [b][m][n]
__device__ float g_Kf[Bz*Mm*Nn];   // softplus(K)  [b][m][n]
__device__ float g_Vp[Bz*Cc*Nn];   // gate * V     [b][c][n]
__device__ float g_KV[Bz*Mm*Cc];   // [b][m][c]
__device__ float g_Ks2[Bz*Mm];     // sum_n Kf + EPS
__device__ float g_gate[Bz*Cc];    // max_n x + mean_n x
__device__ float g_norm[Bz*Nn];    // 1 / (Qf . Ks2)

__device__ __forceinline__ float softplus_f(float v) {
    return fmaxf(v, 0.f) + log1pf(expf(-fabsf(v)));
}

// ---------------- kernel 1: zero KV ----------------
__global__ void zero_kv_kernel() {
    int i = blockIdx.x * 256 + threadIdx.x;
    if (i < Bz*Mm*Cc) g_KV[i] = 0.f;
}

// ---------------- kernel 2: gate = max_n + mean_n over x[b][c][:] ----------------
__global__ __launch_bounds__(256) void gate_kernel(const float* __restrict__ x) {
    int row = blockIdx.x;                 // b*Cc + c
    const float* p = x + (size_t)row * Nn;
    float mx = -INFINITY, sm = 0.f;
    for (int i = threadIdx.x; i < Nn; i += 256) {
        float v = p[i];
        mx = fmaxf(mx, v);
        sm += v;
    }
    #pragma unroll
    for (int o = 16; o; o >>= 1) {
        mx = fmaxf(mx, __shfl_xor_sync(0xffffffffu, mx, o));
        sm += __shfl_xor_sync(0xffffffffu, sm, o);
    }
    __shared__ float smx[8], ssm[8];
    int w = threadIdx.x >> 5, l = threadIdx.x & 31;
    if (l == 0) { smx[w] = mx; ssm[w] = sm; }
    __syncthreads();
    if (threadIdx.x == 0) {
        mx = smx[0]; sm = ssm[0];
        #pragma unroll
        for (int i = 1; i < 8; i++) { mx = fmaxf(mx, smx[i]); sm += ssm[i]; }
        g_gate[row] = mx + sm * (1.f / Nn);
    }
}

// ---------------- kernel 3: fused QKV projection GEMM ----------------
// Out[b][r][n] = sum_c W[r][c] * x[b][c][n] + bias[r],  r in [0,640)
// rows 0..63 -> softplus -> Qf ; 64..127 -> softplus -> Kf ; 128..639 -> gate*V -> Vp
__global__ __launch_bounds__(256) void qkv_gemm_kernel(
    const float* __restrict__ x,
    const float* __restrict__ wq, const float* __restrict__ bq,
    const float* __restrict__ wk, const float* __restrict__ bk,
    const float* __restrict__ wv, const float* __restrict__ bv)
{
    const int b  = blockIdx.z;
    const int r0 = blockIdx.y * 128;
    const int n0 = blockIdx.x * 128;

    __shared__ float As[8][128];   // [k][row]
    __shared__ float Bs[8][128];   // [k][n]

    const float* xb = x + (size_t)b * Cc * Nn;
    const int tid = threadIdx.x;
    const int tx = tid & 15;       // n sub
    const int ty = tid >> 4;       // row sub

    float acc[8][8];
    #pragma unroll
    for (int i = 0; i < 8; i++)
        #pragma unroll
        for (int j = 0; j < 8; j++) acc[i][j] = 0.f;

    // A-load mapping: one float4 per thread
    const int ar = tid >> 1;          // 0..127 local row
    const int ak = (tid & 1) * 4;     // k offset 0 or 4
    const int grow = r0 + ar;
    const float* wrow;
    if (grow < Mm)            wrow = wq + (size_t)grow * Cc;
    else if (grow < 2*Mm)     wrow = wk + (size_t)(grow - Mm) * Cc;
    else                      wrow = wv + (size_t)(grow - 2*Mm) * Cc;

    // B-load mapping: one float4 per thread
    const int bkr = tid >> 5;         // 0..7 (k row)
    const int bn  = (tid & 31) * 4;   // 0..124

    for (int kt = 0; kt < Cc; kt += 8) {
        float4 a4 = *(const float4*)(wrow + kt + ak);
        As[ak + 0][ar] = a4.x;
        As[ak + 1][ar] = a4.y;
        As[ak + 2][ar] = a4.z;
        As[ak + 3][ar] = a4.w;
        float4 b4 = *(const float4*)(xb + (size_t)(kt + bkr) * Nn + n0 + bn);
        *(float4*)&Bs[bkr][bn] = b4;
        __syncthreads();
        #pragma unroll
        for (int kk = 0; kk < 8; kk++) {
            float a0[8], b0[8];
            *(float4*)(a0)     = *(float4*)&As[kk][ty * 8];
            *(float4*)(a0 + 4) = *(float4*)&As[kk][ty * 8 + 4];
            *(float4*)(b0)     = *(float4*)&Bs[kk][tx * 8];
            *(float4*)(b0 + 4) = *(float4*)&Bs[kk][tx * 8 + 4];
            #pragma unroll
            for (int i = 0; i < 8; i++)
                #pragma unroll
                for (int j = 0; j < 8; j++)
                    acc[i][j] = fmaf(a0[i], b0[j], acc[i][j]);
        }
        __syncthreads();
    }

    // epilogue
    #pragma unroll
    for (int i = 0; i < 8; i++) {
        int r = r0 + ty * 8 + i;
        float bias; float* dst; int mode; float gv = 1.f;
        if (r < Mm)        { bias = bq[r];        dst = g_Qf + ((size_t)(b*Mm + r) * Nn);          mode = 0; }
        else if (r < 2*Mm) { bias = bk[r - Mm];   dst = g_Kf + ((size_t)(b*Mm + r - Mm) * Nn);     mode = 0; }
        else               { bias = bv[r - 2*Mm]; dst = g_Vp + ((size_t)(b*Cc + r - 2*Mm) * Nn);
                             gv = g_gate[b*Cc + r - 2*Mm];                                          mode = 1; }
        float v[8];
        #pragma unroll
        for (int j = 0; j < 8; j++) {
            float val = acc[i][j] + bias;
            v[j] = (mode == 0) ? softplus_f(val) : val * gv;
        }
        int n = n0 + tx * 8;
        *(float4*)(dst + n)     = *(float4*)(v);
        *(float4*)(dst + n + 4) = *(float4*)(v + 4);
    }
}

// ---------------- kernel 4: Ksum + EPS ----------------
__global__ __launch_bounds__(256) void ksum_kernel() {
    int row = blockIdx.x;                 // b*Mm + m
    const float* p = g_Kf + (size_t)row * Nn;
    float sm = 0.f;
    for (int i = threadIdx.x; i < Nn; i += 256) sm += p[i];
    #pragma unroll
    for (int o = 16; o; o >>= 1) sm += __shfl_xor_sync(0xffffffffu, sm, o);
    __shared__ float ssm[8];
    int w = threadIdx.x >> 5, l = threadIdx.x & 31;
    if (l == 0) ssm[w] = sm;
    __syncthreads();
    if (threadIdx.x == 0) {
        sm = ssm[0];
        #pragma unroll
        for (int i = 1; i < 8; i++) sm += ssm[i];
        g_Ks2[row] = sm + EPSc;
    }
}

// ---------------- kernel 5: KV[b][m][c] = sum_n Kf[b][m][n] * Vp[b][c][n]  (split-k) ----------------
__global__ __launch_bounds__(256) void kv_kernel() {
    const int b      = blockIdx.z;
    const int c0     = blockIdx.y * 64;
    const int n_base = blockIdx.x * 512;

    __shared__ float Ks[64][33];
    __shared__ float Vs[64][33];

    const float* kf = g_Kf + (size_t)b * Mm * Nn;
    const float* vp = g_Vp + (size_t)b * Cc * Nn;
    const int tid = threadIdx.x;
    const int tx = tid & 15;    // c sub
    const int ty = tid >> 4;    // m sub
    float acc[4][4];
    #pragma unroll
    for (int i = 0; i < 4; i++)
        #pragma unroll
        for (int j = 0; j < 4; j++) acc[i][j] = 0.f;

    for (int nb = 0; nb < 512; nb += 32) {
        const int n0 = n_base + nb;
        __syncthreads();
        #pragma unroll
        for (int i = 0; i < 8; i++) {
            int idx = tid + i * 256;          // 0..2047
            int row = idx >> 5;
            int nn  = idx & 31;
            Ks[row][nn] = kf[(size_t)row * Nn + n0 + nn];
            Vs[row][nn] = vp[(size_t)(c0 + row) * Nn + n0 + nn];
        }
        __syncthreads();
        #pragma unroll
        for (int nn = 0; nn < 32; nn++) {
            float a[4], v[4];
            #pragma unroll
            for (int i = 0; i < 4; i++) a[i] = Ks[ty * 4 + i][nn];
            #pragma unroll
            for (int j = 0; j < 4; j++) v[j] = Vs[tx * 4 + j][nn];
            #pragma unroll
            for (int i = 0; i < 4; i++)
                #pragma unroll
                for (int j = 0; j < 4; j++)
                    acc[i][j] = fmaf(a[i], v[j], acc[i][j]);
        }
    }
    #pragma unroll
    for (int i = 0; i < 4; i++)
        #pragma unroll
        for (int j = 0; j < 4; j++)
            atomicAdd(&g_KV[(size_t)(b*Mm + ty*4 + i) * Cc + c0 + tx*4 + j], acc[i][j]);
}

// ---------------- kernel 6: norm[b][n] = 1 / sum_m Qf[b][m][n] * Ks2[b][m] ----------------
__global__ __launch_bounds__(256) void norm_kernel() {
    int idx = blockIdx.x * 256 + threadIdx.x;    // over Bz*Nn
    int b = idx >> 12;                            // / Nn
    int n = idx & (Nn - 1);
    const float* q  = g_Qf + (size_t)b * Mm * Nn + n;
    const float* ks = g_Ks2 + b * Mm;
    float acc = 0.f;
    #pragma unroll
    for (int m = 0; m < Mm; m++) acc = fmaf(q[(size_t)m * Nn], ks[m], acc);
    g_norm[idx] = 1.f / acc;
}

// ---------------- kernel 7: out = x + gamma * norm * (KV^T @ Qf) ----------------
__global__ __launch_bounds__(256) void out_kernel(const float* __restrict__ x,
                                                  const float* __restrict__ gamma,
                                                  float* __restrict__ out) {
    const int b  = blockIdx.z;
    const int c0 = blockIdx.y * 64;
    const int n0 = blockIdx.x * 64;

    __shared__ float Qs[64][64];    // [m][n]
    __shared__ float KVs[64][64];   // [m][c]

    const float* qb  = g_Qf + (size_t)b * Mm * Nn;
    const float* kvb = g_KV + (size_t)b * Mm * Cc;
    const int tid = threadIdx.x;

    #pragma unroll
    for (int i = 0; i < 4; i++) {
        int idx4 = tid + i * 256;       // 0..1023 float4 index
        int m = idx4 >> 4;              // 16 float4 per row
        int f = (idx4 & 15) * 4;
        *(float4*)&Qs[m][f]  = *(const float4*)(qb  + (size_t)m * Nn + n0 + f);
        *(float4*)&KVs[m][f] = *(const float4*)(kvb + (size_t)m * Cc + c0 + f);
    }
    __syncthreads();

    const int tx = tid & 15;   // n sub
    const int ty = tid >> 4;   // c sub
    float acc[4][4];
    #pragma unroll
    for (int i = 0; i < 4; i++)
        #pragma unroll
        for (int j = 0; j < 4; j++) acc[i][j] = 0.f;

    #pragma unroll
    for (int m = 0; m < 64; m++) {
        float a[4], q[4];
        *(float4*)a = *(float4*)&KVs[m][ty * 4];
        *(float4*)q = *(float4*)&Qs[m][tx * 4];
        #pragma unroll
        for (int i = 0; i < 4; i++)
            #pragma unroll
            for (int j = 0; j < 4; j++)
                acc[i][j] = fmaf(a[i], q[j], acc[i][j]);
    }

    const float g = gamma[0];
    float nr[4];
    #pragma unroll
    for (int j = 0; j < 4; j++) nr[j] = g_norm[b * Nn + n0 + tx * 4 + j];

    #pragma unroll
    for (int i = 0; i < 4; i++) {
        int c = c0 + ty * 4 + i;
        size_t off = ((size_t)(b * Cc + c)) * Nn + n0 + tx * 4;
        float4 xv = *(const float4*)(x + off);
        float4 r;
        r.x = xv.x + g * nr[0] * acc[i][0];
        r.y = xv.y + g * nr[1] * acc[i][1];
        r.z = xv.z + g * nr[2] * acc[i][2];
        r.w = xv.w + g * nr[3] * acc[i][3];
        *(float4*)(out + off) = r;
    }
}

// ---------------- launch ----------------
extern "C" void kernel_launch(void* const* d_in, const int* in_sizes, int n_in,
                              void* d_out, int out_size) {
    const float* x     = (const float*)d_in[0];
    const float* wq    = (const float*)d_in[1];
    const float* bq    = (const float*)d_in[2];
    const float* wk    = (const float*)d_in[3];
    const float* bk    = (const float*)d_in[4];
    const float* wv    = (const float*)d_in[5];
    const float* bv    = (const float*)d_in[6];
    const float* gamma = (const float*)d_in[7];
    float* out = (float*)d_out;

    zero_kv_kernel<<<(Bz*Mm*Cc + 255) / 256, 256>>>();
    gate_kernel<<<Bz * Cc, 256>>>(x);
    qkv_gemm_kernel<<<dim3(Nn / 128, Rr / 128, Bz), 256>>>(x, wq, bq, wk, bk, wv, bv);
    ksum_kernel<<<Bz * Mm, 256>>>();
    kv_kernel<<<dim3(Nn / 512, Cc / 64, Bz), 256>>>();
    norm_kernel<<<Bz * Nn / 256, 256>>>();
    out_kernel<<<dim3(Nn / 64, Cc / 64, Bz), 256>>>(x, gamma, out);
}

// round 4
// speedup vs baseline: 2.0218x; 2.0218x over previous
#include <cuda_runtime.h>
#include <math.h>
#include <stdint.h>

#define Bz   8
#define Cc   512
#define Nn   4096
#define Mm   64
#define Rr   640        // Mm + Mm + Cc
#define EPSc 1e-6f

// ---------------- device scratch ----------------
__device__ float g_Qf[Bz*Mm*Nn];   // softplus(Q)  [b][m][n]
__device__ float g_Kf[Bz*Mm*Nn];   // softplus(K)  [b][m][n]
__device__ float g_Vp[Bz*Cc*Nn];   // gate * V     [b][c][n]
__device__ float g_xT[Bz*Nn*Cc];   // x transposed [b][n][c]
__device__ float g_Wcat[Rr*Cc];    // packed weights [r][c]
__device__ float g_bias[Rr];
__device__ float g_KV[Bz*Mm*Cc];   // [b][m][c]
__device__ float g_Ks2[Bz*Mm];     // sum_n Kf (EPS added in norm)
__device__ float g_gate[Bz*Cc];
__device__ float g_norm[Bz*Nn];

// ---------------- tf32 mma.sync helpers (sm_80+, works on base sm_100) ----------------
__device__ __forceinline__ uint32_t f2tf32(float f) {
    uint32_t r;
    asm("cvt.rna.tf32.f32 %0, %1;" : "=r"(r) : "f"(f));
    return r;
}
__device__ __forceinline__ void mma_tf32(float* d, const uint32_t* a, const uint32_t* b) {
    asm volatile(
        "mma.sync.aligned.m16n8k8.row.col.f32.tf32.tf32.f32 "
        "{%0,%1,%2,%3}, {%4,%5,%6,%7}, {%8,%9}, {%0,%1,%2,%3};"
        : "+f"(d[0]), "+f"(d[1]), "+f"(d[2]), "+f"(d[3])
        : "r"(a[0]), "r"(a[1]), "r"(a[2]), "r"(a[3]), "r"(b[0]), "r"(b[1]));
}

// ---------------- kernel: zero KV + Ks2 ----------------
__global__ void zero_kernel() {
    int i = blockIdx.x * 256 + threadIdx.x;
    if (i < Bz*Mm*Cc) g_KV[i] = 0.f;
    if (i < Bz*Mm) g_Ks2[i] = 0.f;
}

// ---------------- kernel: pack W + bias ----------------
__global__ void pack_kernel(const float* __restrict__ wq, const float* __restrict__ bq,
                            const float* __restrict__ wk, const float* __restrict__ bk,
                            const float* __restrict__ wv, const float* __restrict__ bv) {
    int i = blockIdx.x * 256 + threadIdx.x;
    if (i < Rr*Cc) {
        float v;
        if (i < Mm*Cc)          v = wq[i];
        else if (i < 2*Mm*Cc)   v = wk[i - Mm*Cc];
        else                    v = wv[i - 2*Mm*Cc];
        g_Wcat[i] = v;
    } else if (i < Rr*Cc + Rr) {
        int r = i - Rr*Cc;
        float v;
        if (r < Mm)        v = bq[r];
        else if (r < 2*Mm) v = bk[r - Mm];
        else               v = bv[r - 2*Mm];
        g_bias[r] = v;
    }
}

// ---------------- kernel: transpose x -> xT[b][n][c] ----------------
__global__ __launch_bounds__(256) void transpose_kernel(const float* __restrict__ x) {
    __shared__ float ts[64][65];
    const int n0 = blockIdx.x * 64;
    const int c0 = blockIdx.y * 64;
    const int b  = blockIdx.z;
    const int tid = threadIdx.x;
    #pragma unroll
    for (int p = 0; p < 4; p++) {
        int idx = tid + p*256;
        int cl = idx >> 4;
        int n4 = (idx & 15) * 4;
        float4 v = *(const float4*)(x + ((size_t)(b*Cc + c0 + cl))*Nn + n0 + n4);
        ts[cl][n4+0] = v.x; ts[cl][n4+1] = v.y; ts[cl][n4+2] = v.z; ts[cl][n4+3] = v.w;
    }
    __syncthreads();
    #pragma unroll
    for (int p = 0; p < 4; p++) {
        int idx = tid + p*256;
        int nl = idx >> 4;
        int c4 = (idx & 15) * 4;
        float4 w;
        w.x = ts[c4+0][nl]; w.y = ts[c4+1][nl]; w.z = ts[c4+2][nl]; w.w = ts[c4+3][nl];
        *(float4*)(g_xT + ((size_t)(b*Nn + n0 + nl))*Cc + c0 + c4) = w;
    }
}

// ---------------- kernel: gate ----------------
__global__ __launch_bounds__(256) void gate_kernel(const float* __restrict__ x) {
    int row = blockIdx.x;
    const float* p = x + (size_t)row * Nn;
    float mx = -INFINITY, sm = 0.f;
    for (int i = threadIdx.x; i < Nn; i += 256) {
        float v = p[i];
        mx = fmaxf(mx, v);
        sm += v;
    }
    #pragma unroll
    for (int o = 16; o; o >>= 1) {
        mx = fmaxf(mx, __shfl_xor_sync(0xffffffffu, mx, o));
        sm += __shfl_xor_sync(0xffffffffu, sm, o);
    }
    __shared__ float smx[8], ssm[8];
    int w = threadIdx.x >> 5, l = threadIdx.x & 31;
    if (l == 0) { smx[w] = mx; ssm[w] = sm; }
    __syncthreads();
    if (threadIdx.x == 0) {
        mx = smx[0]; sm = ssm[0];
        #pragma unroll
        for (int i = 1; i < 8; i++) { mx = fmaxf(mx, smx[i]); sm += ssm[i]; }
        g_gate[row] = mx + sm * (1.f / Nn);
    }
}

// ---------------- kernel: tf32 mma.sync QKV GEMM ----------------
// D[r][n] = sum_c Wcat[r][c] * xT[b][n][c]   (A row-major, B = xT "col" layout)
// CTA: 128 r x 128 n, K chunks of 32. 8 warps in 4(M) x 2(N), warp tile 32x64.
__global__ __launch_bounds__(256, 2) void qkv_mma_kernel() {
    __shared__ uint32_t As[128][36];   // [r][k] tf32 bits, pad 4
    __shared__ uint32_t Bs[128][36];   // [n][k] tf32 bits

    const int tid = threadIdx.x;
    const int wid = tid >> 5;
    const int lid = tid & 31;
    const int g4  = lid >> 2;
    const int l4  = lid & 3;
    const int wm  = wid >> 1;          // 0..3
    const int wn  = wid & 1;           // 0..1

    const int n0 = blockIdx.x * 128;
    const int r0 = blockIdx.y * 128;
    const int b  = blockIdx.z;

    const float* aptr = g_Wcat + (size_t)r0 * Cc;
    const float* bptr = g_xT + ((size_t)b * Nn + n0) * Cc;

    float acc[2][8][4];
    #pragma unroll
    for (int mi = 0; mi < 2; mi++)
        #pragma unroll
        for (int ni = 0; ni < 8; ni++)
            #pragma unroll
            for (int q = 0; q < 4; q++) acc[mi][ni][q] = 0.f;

    const int lrow = tid >> 3;          // 0..31 load row sub
    const int lf   = (tid & 7) * 4;     // float4 col offset

    for (int kc = 0; kc < Cc; kc += 32) {
        __syncthreads();
        #pragma unroll
        for (int p = 0; p < 4; p++) {
            int row = lrow + p * 32;
            float4 va = *(const float4*)(aptr + (size_t)row * Cc + kc + lf);
            uint4 ua = { f2tf32(va.x), f2tf32(va.y), f2tf32(va.z), f2tf32(va.w) };
            *(uint4*)&As[row][lf] = ua;
            float4 vb = *(const float4*)(bptr + (size_t)row * Cc + kc + lf);
            uint4 ub = { f2tf32(vb.x), f2tf32(vb.y), f2tf32(vb.z), f2tf32(vb.w) };
            *(uint4*)&Bs[row][lf] = ub;
        }
        __syncthreads();
        #pragma unroll
        for (int k8 = 0; k8 < 4; k8++) {
            const int kb = k8 * 8;
            uint32_t afr[2][4];
            #pragma unroll
            for (int mi = 0; mi < 2; mi++) {
                int mr = wm * 32 + mi * 16;
                afr[mi][0] = As[mr + g4    ][kb + l4];
                afr[mi][1] = As[mr + g4 + 8][kb + l4];
                afr[mi][2] = As[mr + g4    ][kb + l4 + 4];
                afr[mi][3] = As[mr + g4 + 8][kb + l4 + 4];
            }
            uint32_t bfr[8][2];
            #pragma unroll
            for (int ni = 0; ni < 8; ni++) {
                int nr = wn * 64 + ni * 8 + g4;
                bfr[ni][0] = Bs[nr][kb + l4];
                bfr[ni][1] = Bs[nr][kb + l4 + 4];
            }
            #pragma unroll
            for (int mi = 0; mi < 2; mi++)
                #pragma unroll
                for (int ni = 0; ni < 8; ni++)
                    mma_tf32(acc[mi][ni], afr[mi], bfr[ni]);
        }
    }

    // -------- epilogue: bias + softplus/gate, fused ksum --------
    #pragma unroll
    for (int mi = 0; mi < 2; mi++) {
        #pragma unroll
        for (int h = 0; h < 2; h++) {
            const int r = r0 + wm * 32 + mi * 16 + h * 8 + g4;
            const float bias = g_bias[r];
            float* dst; int mode; float gv = 1.f;
            if (r < Mm)        { dst = g_Qf + (size_t)(b*Mm + r) * Nn;        mode = 0; }
            else if (r < 2*Mm) { dst = g_Kf + (size_t)(b*Mm + r - Mm) * Nn;   mode = 1; }
            else               { dst = g_Vp + (size_t)(b*Cc + r - 2*Mm) * Nn; mode = 2;
                                 gv = g_gate[b*Cc + r - 2*Mm]; }
            float ks = 0.f;
            #pragma unroll
            for (int ni = 0; ni < 8; ni++) {
                float v0 = acc[mi][ni][h*2 + 0] + bias;
                float v1 = acc[mi][ni][h*2 + 1] + bias;
                if (mode == 2) { v0 *= gv; v1 *= gv; }
                else {
                    v0 = fmaxf(v0, 0.f) + __logf(1.f + __expf(-fabsf(v0)));
                    v1 = fmaxf(v1, 0.f) + __logf(1.f + __expf(-fabsf(v1)));
                    if (mode == 1) ks += v0 + v1;
                }
                int col = n0 + wn * 64 + ni * 8 + l4 * 2;
                float2 w2 = { v0, v1 };
                *(float2*)(dst + col) = w2;
            }
            if (mode == 1) {
                ks += __shfl_xor_sync(0xffffffffu, ks, 1);
                ks += __shfl_xor_sync(0xffffffffu, ks, 2);
                if (l4 == 0) atomicAdd(&g_Ks2[b*Mm + (r - Mm)], ks);
            }
        }
    }
}

// ---------------- kernel: KV[b][m][c] = sum_n Kf*Vp (split-k FFMA) ----------------
__global__ __launch_bounds__(256) void kv_kernel() {
    const int b      = blockIdx.z;
    const int c0     = blockIdx.y * 64;
    const int n_base = blockIdx.x * 512;
    __shared__ float Ks[64][33];
    __shared__ float Vs[64][33];
    const float* kf = g_Kf + (size_t)b * Mm * Nn;
    const float* vp = g_Vp + (size_t)b * Cc * Nn;
    const int tid = threadIdx.x;
    const int tx = tid & 15;
    const int ty = tid >> 4;
    float acc[4][4];
    #pragma unroll
    for (int i = 0; i < 4; i++)
        #pragma unroll
        for (int j = 0; j < 4; j++) acc[i][j] = 0.f;
    for (int nb = 0; nb < 512; nb += 32) {
        const int n0 = n_base + nb;
        __syncthreads();
        #pragma unroll
        for (int i = 0; i < 8; i++) {
            int idx = tid + i * 256;
            int row = idx >> 5;
            int nn  = idx & 31;
            Ks[row][nn] = kf[(size_t)row * Nn + n0 + nn];
            Vs[row][nn] = vp[(size_t)(c0 + row) * Nn + n0 + nn];
        }
        __syncthreads();
        #pragma unroll
        for (int nn = 0; nn < 32; nn++) {
            float a[4], v[4];
            #pragma unroll
            for (int i = 0; i < 4; i++) a[i] = Ks[ty * 4 + i][nn];
            #pragma unroll
            for (int j = 0; j < 4; j++) v[j] = Vs[tx * 4 + j][nn];
            #pragma unroll
            for (int i = 0; i < 4; i++)
                #pragma unroll
                for (int j = 0; j < 4; j++)
                    acc[i][j] = fmaf(a[i], v[j], acc[i][j]);
        }
    }
    #pragma unroll
    for (int i = 0; i < 4; i++)
        #pragma unroll
        for (int j = 0; j < 4; j++)
            atomicAdd(&g_KV[(size_t)(b*Mm + ty*4 + i) * Cc + c0 + tx*4 + j], acc[i][j]);
}

// ---------------- kernel: norm ----------------
__global__ __launch_bounds__(256) void norm_kernel() {
    int idx = blockIdx.x * 256 + threadIdx.x;
    int b = idx >> 12;
    int n = idx & (Nn - 1);
    const float* q  = g_Qf + (size_t)b * Mm * Nn + n;
    const float* ks = g_Ks2 + b * Mm;
    float acc = 0.f;
    #pragma unroll
    for (int m = 0; m < Mm; m++) acc = fmaf(q[(size_t)m * Nn], ks[m] + EPSc, acc);
    g_norm[idx] = 1.f / acc;
}

// ---------------- kernel: out = x + gamma * norm * (KV^T @ Qf) ----------------
__global__ __launch_bounds__(256) void out_kernel(const float* __restrict__ x,
                                                  const float* __restrict__ gamma,
                                                  float* __restrict__ out) {
    const int b  = blockIdx.z;
    const int c0 = blockIdx.y * 64;
    const int n0 = blockIdx.x * 64;
    __shared__ float Qs[64][64];
    __shared__ float KVs[64][64];
    const float* qb  = g_Qf + (size_t)b * Mm * Nn;
    const float* kvb = g_KV + (size_t)b * Mm * Cc;
    const int tid = threadIdx.x;
    #pragma unroll
    for (int i = 0; i < 4; i++) {
        int idx4 = tid + i * 256;
        int m = idx4 >> 4;
        int f = (idx4 & 15) * 4;
        *(float4*)&Qs[m][f]  = *(const float4*)(qb  + (size_t)m * Nn + n0 + f);
        *(float4*)&KVs[m][f] = *(const float4*)(kvb + (size_t)m * Cc + c0 + f);
    }
    __syncthreads();
    const int tx = tid & 15;
    const int ty = tid >> 4;
    float acc[4][4];
    #pragma unroll
    for (int i = 0; i < 4; i++)
        #pragma unroll
        for (int j = 0; j < 4; j++) acc[i][j] = 0.f;
    #pragma unroll
    for (int m = 0; m < 64; m++) {
        float a[4], q[4];
        *(float4*)a = *(float4*)&KVs[m][ty * 4];
        *(float4*)q = *(float4*)&Qs[m][tx * 4];
        #pragma unroll
        for (int i = 0; i < 4; i++)
            #pragma unroll
            for (int j = 0; j < 4; j++)
                acc[i][j] = fmaf(a[i], q[j], acc[i][j]);
    }
    const float g = gamma[0];
    float nr[4];
    #pragma unroll
    for (int j = 0; j < 4; j++) nr[j] = g_norm[b * Nn + n0 + tx * 4 + j];
    #pragma unroll
    for (int i = 0; i < 4; i++) {
        int c = c0 + ty * 4 + i;
        size_t off = ((size_t)(b * Cc + c)) * Nn + n0 + tx * 4;
        float4 xv = *(const float4*)(x + off);
        float4 r;
        r.x = xv.x + g * nr[0] * acc[i][0];
        r.y = xv.y + g * nr[1] * acc[i][1];
        r.z = xv.z + g * nr[2] * acc[i][2];
        r.w = xv.w + g * nr[3] * acc[i][3];
        *(float4*)(out + off) = r;
    }
}

// ---------------- launch ----------------
extern "C" void kernel_launch(void* const* d_in, const int* in_sizes, int n_in,
                              void* d_out, int out_size) {
    const float* x     = (const float*)d_in[0];
    const float* wq    = (const float*)d_in[1];
    const float* bq    = (const float*)d_in[2];
    const float* wk    = (const float*)d_in[3];
    const float* bk    = (const float*)d_in[4];
    const float* wv    = (const float*)d_in[5];
    const float* bv    = (const float*)d_in[6];
    const float* gamma = (const float*)d_in[7];
    float* out = (float*)d_out;

    zero_kernel<<<(Bz*Mm*Cc + 255) / 256, 256>>>();
    pack_kernel<<<(Rr*Cc + Rr + 255) / 256, 256>>>(wq, bq, wk, bk, wv, bv);
    transpose_kernel<<<dim3(Nn/64, Cc/64, Bz), 256>>>(x);
    gate_kernel<<<Bz * Cc, 256>>>(x);
    qkv_mma_kernel<<<dim3(Nn/128, Rr/128, Bz), 256>>>();
    kv_kernel<<<dim3(Nn/512, Cc/64, Bz), 256>>>();
    norm_kernel<<<Bz * Nn / 256, 256>>>();
    out_kernel<<<dim3(Nn/64, Cc/64, Bz), 256>>>(x, gamma, out);
}

// round 5
// speedup vs baseline: 2.8479x; 1.4086x over previous
#include <cuda_runtime.h>
#include <math.h>
#include <stdint.h>

#define Bz   8
#define Cc   512
#define Nn   4096
#define Mm   64
#define Rr   640        // Mm + Mm + Cc
#define EPSc 1e-6f

// ---------------- device scratch ----------------
__device__ float g_Qf[Bz*Mm*Nn];   // softplus(Q)  [b][m][n]
__device__ float g_Kf[Bz*Mm*Nn];   // softplus(K)  [b][m][n]
__device__ float g_Vp[Bz*Cc*Nn];   // gate * V     [b][c][n]
__device__ float g_xT[Bz*Nn*Cc];   // x transposed [b][n][c]
__device__ float g_Wcat[Rr*Cc];    // packed weights [r][c]
__device__ float g_bias[Rr];
__device__ float g_KV[Bz*Mm*Cc];   // [b][m][c]
__device__ float g_Ks2[Bz*Mm];     // sum_n Kf (EPS added in norm)
__device__ float g_gmax[Bz*Cc];    // atomic max partials
__device__ float g_gsum[Bz*Cc];    // atomic sum partials
__device__ float g_gate[Bz*Cc];
__device__ float g_norm[Bz*Nn];

// ---------------- tf32 mma.sync helpers (sm_80+, works on base sm_100) ----------------
__device__ __forceinline__ uint32_t f2tf32(float f) {
    uint32_t r;
    asm("cvt.rna.tf32.f32 %0, %1;" : "=r"(r) : "f"(f));
    return r;
}
__device__ __forceinline__ void mma_tf32(float* d, const uint32_t* a, const uint32_t* b) {
    asm volatile(
        "mma.sync.aligned.m16n8k8.row.col.f32.tf32.tf32.f32 "
        "{%0,%1,%2,%3}, {%4,%5,%6,%7}, {%8,%9}, {%0,%1,%2,%3};"
        : "+f"(d[0]), "+f"(d[1]), "+f"(d[2]), "+f"(d[3])
        : "r"(a[0]), "r"(a[1]), "r"(a[2]), "r"(a[3]), "r"(b[0]), "r"(b[1]));
}
// monotone float atomic max (works for mixed signs; init -inf)
__device__ __forceinline__ void atomicMaxF(float* addr, float v) {
    if (v >= 0.f) atomicMax((int*)addr, __float_as_int(v));
    else          atomicMin((unsigned int*)addr, __float_as_uint(v));
}

// ---------------- kernel: zero scratch ----------------
__global__ void zero_kernel() {
    int i = blockIdx.x * 256 + threadIdx.x;
    if (i < Bz*Mm*Cc) g_KV[i] = 0.f;
    if (i < Bz*Mm) g_Ks2[i] = 0.f;
    if (i < Bz*Cc) { g_gmax[i] = -INFINITY; g_gsum[i] = 0.f; }
}

// ---------------- kernel: pack W + bias ----------------
__global__ void pack_kernel(const float* __restrict__ wq, const float* __restrict__ bq,
                            const float* __restrict__ wk, const float* __restrict__ bk,
                            const float* __restrict__ wv, const float* __restrict__ bv) {
    int i = blockIdx.x * 256 + threadIdx.x;
    if (i < Rr*Cc) {
        float v;
        if (i < Mm*Cc)          v = wq[i];
        else if (i < 2*Mm*Cc)   v = wk[i - Mm*Cc];
        else                    v = wv[i - 2*Mm*Cc];
        g_Wcat[i] = v;
    } else if (i < Rr*Cc + Rr) {
        int r = i - Rr*Cc;
        float v;
        if (r < Mm)        v = bq[r];
        else if (r < 2*Mm) v = bk[r - Mm];
        else               v = bv[r - 2*Mm];
        g_bias[r] = v;
    }
}

// ---------------- kernel: transpose x -> xT[b][n][c], fused gate partials ----------------
__global__ __launch_bounds__(256) void transpose_kernel(const float* __restrict__ x) {
    __shared__ float ts[64][65];
    const int n0 = blockIdx.x * 64;
    const int c0 = blockIdx.y * 64;
    const int b  = blockIdx.z;
    const int tid = threadIdx.x;
    #pragma unroll
    for (int p = 0; p < 4; p++) {
        int idx = tid + p*256;
        int cl = idx >> 4;
        int n4 = (idx & 15) * 4;
        float4 v = *(const float4*)(x + ((size_t)(b*Cc + c0 + cl))*Nn + n0 + n4);
        ts[cl][n4+0] = v.x; ts[cl][n4+1] = v.y; ts[cl][n4+2] = v.z; ts[cl][n4+3] = v.w;
    }
    __syncthreads();
    // gate partial reduction: 4 threads per c-row
    {
        int c = tid >> 2, q = tid & 3;
        float mx = -INFINITY, sm = 0.f;
        #pragma unroll
        for (int i = 0; i < 16; i++) {
            float v = ts[c][q*16 + i];
            mx = fmaxf(mx, v); sm += v;
        }
        mx = fmaxf(mx, __shfl_xor_sync(0xffffffffu, mx, 1));
        sm += __shfl_xor_sync(0xffffffffu, sm, 1);
        mx = fmaxf(mx, __shfl_xor_sync(0xffffffffu, mx, 2));
        sm += __shfl_xor_sync(0xffffffffu, sm, 2);
        if (q == 0) {
            atomicMaxF(&g_gmax[b*Cc + c0 + c], mx);
            atomicAdd(&g_gsum[b*Cc + c0 + c], sm);
        }
    }
    // transposed write
    #pragma unroll
    for (int p = 0; p < 4; p++) {
        int idx = tid + p*256;
        int nl = idx >> 4;
        int c4 = (idx & 15) * 4;
        float4 w;
        w.x = ts[c4+0][nl]; w.y = ts[c4+1][nl]; w.z = ts[c4+2][nl]; w.w = ts[c4+3][nl];
        *(float4*)(g_xT + ((size_t)(b*Nn + n0 + nl))*Cc + c0 + c4) = w;
    }
}

// ---------------- kernel: finalize gate ----------------
__global__ void gate_fin_kernel() {
    int i = blockIdx.x * 256 + threadIdx.x;
    if (i < Bz*Cc) g_gate[i] = g_gmax[i] + g_gsum[i] * (1.f / Nn);
}

// ---------------- kernel: tf32 mma.sync QKV GEMM (B-stream prefetch) ----------------
// D[r][n] = sum_c Wcat[r][c] * xT[b][n][c]
__global__ __launch_bounds__(256, 2) void qkv_mma_kernel() {
    __shared__ uint32_t As[128][36];   // [r][k]
    __shared__ uint32_t Bs[128][36];   // [n][k]

    const int tid = threadIdx.x;
    const int wid = tid >> 5;
    const int lid = tid & 31;
    const int g4  = lid >> 2;
    const int l4  = lid & 3;
    const int wm  = wid >> 1;
    const int wn  = wid & 1;

    const int n0 = blockIdx.x * 128;
    const int r0 = blockIdx.y * 128;
    const int b  = blockIdx.z;

    const float* aptr = g_Wcat + (size_t)r0 * Cc;
    const float* bptr = g_xT + ((size_t)b * Nn + n0) * Cc;

    float acc[2][8][4];
    #pragma unroll
    for (int mi = 0; mi < 2; mi++)
        #pragma unroll
        for (int ni = 0; ni < 8; ni++)
            #pragma unroll
            for (int q = 0; q < 4; q++) acc[mi][ni][q] = 0.f;

    const int lrow = tid >> 3;
    const int lf   = (tid & 7) * 4;

    float4 pb[4];
    #pragma unroll
    for (int p = 0; p < 4; p++)
        pb[p] = *(const float4*)(bptr + (size_t)(lrow + p*32) * Cc + lf);

    for (int kc = 0; kc < Cc; kc += 32) {
        if (kc) __syncthreads();
        #pragma unroll
        for (int p = 0; p < 4; p++) {
            int row = lrow + p * 32;
            float4 va = *(const float4*)(aptr + (size_t)row * Cc + kc + lf);
            uint4 ua = { f2tf32(va.x), f2tf32(va.y), f2tf32(va.z), f2tf32(va.w) };
            *(uint4*)&As[row][lf] = ua;
            uint4 ub = { f2tf32(pb[p].x), f2tf32(pb[p].y), f2tf32(pb[p].z), f2tf32(pb[p].w) };
            *(uint4*)&Bs[row][lf] = ub;
        }
        __syncthreads();
        if (kc + 32 < Cc) {
            #pragma unroll
            for (int p = 0; p < 4; p++)
                pb[p] = *(const float4*)(bptr + (size_t)(lrow + p*32) * Cc + kc + 32 + lf);
        }
        #pragma unroll
        for (int k8 = 0; k8 < 4; k8++) {
            const int kb = k8 * 8;
            uint32_t afr[2][4];
            #pragma unroll
            for (int mi = 0; mi < 2; mi++) {
                int mr = wm * 32 + mi * 16;
                afr[mi][0] = As[mr + g4    ][kb + l4];
                afr[mi][1] = As[mr + g4 + 8][kb + l4];
                afr[mi][2] = As[mr + g4    ][kb + l4 + 4];
                afr[mi][3] = As[mr + g4 + 8][kb + l4 + 4];
            }
            uint32_t bfr[8][2];
            #pragma unroll
            for (int ni = 0; ni < 8; ni++) {
                int nr = wn * 64 + ni * 8 + g4;
                bfr[ni][0] = Bs[nr][kb + l4];
                bfr[ni][1] = Bs[nr][kb + l4 + 4];
            }
            #pragma unroll
            for (int mi = 0; mi < 2; mi++)
                #pragma unroll
                for (int ni = 0; ni < 8; ni++)
                    mma_tf32(acc[mi][ni], afr[mi], bfr[ni]);
        }
    }

    // -------- epilogue: bias + softplus/gate, fused ksum --------
    #pragma unroll
    for (int mi = 0; mi < 2; mi++) {
        #pragma unroll
        for (int h = 0; h < 2; h++) {
            const int r = r0 + wm * 32 + mi * 16 + h * 8 + g4;
            const float bias = g_bias[r];
            float* dst; int mode; float gv = 1.f;
            if (r < Mm)        { dst = g_Qf + (size_t)(b*Mm + r) * Nn;        mode = 0; }
            else if (r < 2*Mm) { dst = g_Kf + (size_t)(b*Mm + r - Mm) * Nn;   mode = 1; }
            else               { dst = g_Vp + (size_t)(b*Cc + r - 2*Mm) * Nn; mode = 2;
                                 gv = g_gate[b*Cc + r - 2*Mm]; }
            float ks = 0.f;
            #pragma unroll
            for (int ni = 0; ni < 8; ni++) {
                float v0 = acc[mi][ni][h*2 + 0] + bias;
                float v1 = acc[mi][ni][h*2 + 1] + bias;
                if (mode == 2) { v0 *= gv; v1 *= gv; }
                else {
                    v0 = fmaxf(v0, 0.f) + __logf(1.f + __expf(-fabsf(v0)));
                    v1 = fmaxf(v1, 0.f) + __logf(1.f + __expf(-fabsf(v1)));
                    if (mode == 1) ks += v0 + v1;
                }
                int col = n0 + wn * 64 + ni * 8 + l4 * 2;
                float2 w2 = { v0, v1 };
                *(float2*)(dst + col) = w2;
            }
            if (mode == 1) {
                ks += __shfl_xor_sync(0xffffffffu, ks, 1);
                ks += __shfl_xor_sync(0xffffffffu, ks, 2);
                if (l4 == 0) atomicAdd(&g_Ks2[b*Mm + (r - Mm)], ks);
            }
        }
    }
}

// ---------------- kernel: KV via tf32 mma, split-k over n ----------------
// KV[b][m][c] = sum_n Kf[b][m][n] * Vp[b][c][n]
__global__ __launch_bounds__(256, 2) void kv_mma_kernel() {
    __shared__ uint32_t As[64][36];    // [m][k]
    __shared__ uint32_t Bs[128][36];   // [c][k]

    const int tid = threadIdx.x;
    const int wid = tid >> 5;
    const int lid = tid & 31;
    const int g4  = lid >> 2;
    const int l4  = lid & 3;
    const int wm  = wid >> 2;          // 0..1
    const int wn  = wid & 3;           // 0..3

    const int b     = blockIdx.z;
    const int c0    = blockIdx.y * 128;
    const int nbase = blockIdx.x * 1024;

    const float* kf = g_Kf + (size_t)b * Mm * Nn;
    const float* vp = g_Vp + ((size_t)(b*Cc + c0)) * Nn;

    float acc[2][4][4];
    #pragma unroll
    for (int mi = 0; mi < 2; mi++)
        #pragma unroll
        for (int ni = 0; ni < 4; ni++)
            #pragma unroll
            for (int q = 0; q < 4; q++) acc[mi][ni][q] = 0.f;

    const int lrow = tid >> 3;
    const int lf   = (tid & 7) * 4;

    float4 pa[2], pb[4];
    #pragma unroll
    for (int p = 0; p < 2; p++)
        pa[p] = *(const float4*)(kf + (size_t)(lrow + p*32) * Nn + nbase + lf);
    #pragma unroll
    for (int p = 0; p < 4; p++)
        pb[p] = *(const float4*)(vp + (size_t)(lrow + p*32) * Nn + nbase + lf);

    for (int nc = 0; nc < 1024; nc += 32) {
        if (nc) __syncthreads();
        #pragma unroll
        for (int p = 0; p < 2; p++) {
            int row = lrow + p * 32;
            uint4 ua = { f2tf32(pa[p].x), f2tf32(pa[p].y), f2tf32(pa[p].z), f2tf32(pa[p].w) };
            *(uint4*)&As[row][lf] = ua;
        }
        #pragma unroll
        for (int p = 0; p < 4; p++) {
            int row = lrow + p * 32;
            uint4 ub = { f2tf32(pb[p].x), f2tf32(pb[p].y), f2tf32(pb[p].z), f2tf32(pb[p].w) };
            *(uint4*)&Bs[row][lf] = ub;
        }
        __syncthreads();
        if (nc + 32 < 1024) {
            int n = nbase + nc + 32;
            #pragma unroll
            for (int p = 0; p < 2; p++)
                pa[p] = *(const float4*)(kf + (size_t)(lrow + p*32) * Nn + n + lf);
            #pragma unroll
            for (int p = 0; p < 4; p++)
                pb[p] = *(const float4*)(vp + (size_t)(lrow + p*32) * Nn + n + lf);
        }
        #pragma unroll
        for (int k8 = 0; k8 < 4; k8++) {
            const int kb = k8 * 8;
            uint32_t afr[2][4];
            #pragma unroll
            for (int mi = 0; mi < 2; mi++) {
                int mr = wm * 32 + mi * 16;
                afr[mi][0] = As[mr + g4    ][kb + l4];
                afr[mi][1] = As[mr + g4 + 8][kb + l4];
                afr[mi][2] = As[mr + g4    ][kb + l4 + 4];
                afr[mi][3] = As[mr + g4 + 8][kb + l4 + 4];
            }
            uint32_t bfr[4][2];
            #pragma unroll
            for (int ni = 0; ni < 4; ni++) {
                int nr = wn * 32 + ni * 8 + g4;
                bfr[ni][0] = Bs[nr][kb + l4];
                bfr[ni][1] = Bs[nr][kb + l4 + 4];
            }
            #pragma unroll
            for (int mi = 0; mi < 2; mi++)
                #pragma unroll
                for (int ni = 0; ni < 4; ni++)
                    mma_tf32(acc[mi][ni], afr[mi], bfr[ni]);
        }
    }

    #pragma unroll
    for (int mi = 0; mi < 2; mi++) {
        #pragma unroll
        for (int h = 0; h < 2; h++) {
            const int m = wm * 32 + mi * 16 + h * 8 + g4;
            float* kvrow = g_KV + (size_t)(b*Mm + m) * Cc + c0;
            #pragma unroll
            for (int ni = 0; ni < 4; ni++) {
                int c = wn * 32 + ni * 8 + l4 * 2;
                atomicAdd(kvrow + c,     acc[mi][ni][h*2 + 0]);
                atomicAdd(kvrow + c + 1, acc[mi][ni][h*2 + 1]);
            }
        }
    }
}

// ---------------- kernel: norm ----------------
__global__ __launch_bounds__(256) void norm_kernel() {
    int idx = blockIdx.x * 256 + threadIdx.x;
    int b = idx >> 12;
    int n = idx & (Nn - 1);
    const float* q  = g_Qf + (size_t)b * Mm * Nn + n;
    const float* ks = g_Ks2 + b * Mm;
    float acc = 0.f;
    #pragma unroll
    for (int m = 0; m < Mm; m++) acc = fmaf(q[(size_t)m * Nn], ks[m] + EPSc, acc);
    g_norm[idx] = 1.f / acc;
}

// ---------------- kernel: out = x + gamma * norm * (KV^T @ Qf)  [tf32 mma, k=64] ----------------
#define OUT_STRIDE 136
#define OUT_SMEM (2 * 64 * OUT_STRIDE * 4)
__global__ __launch_bounds__(256) void out_mma_kernel(const float* __restrict__ x,
                                                      const float* __restrict__ gamma,
                                                      float* __restrict__ out) {
    extern __shared__ uint32_t osm[];
    uint32_t* Qs  = osm;                      // [m][n]  64 x 136
    uint32_t* KVs = osm + 64 * OUT_STRIDE;    // [m][c]  64 x 136

    const int tid = threadIdx.x;
    const int wid = tid >> 5;
    const int lid = tid & 31;
    const int g4  = lid >> 2;
    const int l4  = lid & 3;
    const int wm  = wid >> 1;          // 0..3  (c)
    const int wn  = wid & 1;           // 0..1  (n)

    const int n0 = blockIdx.x * 128;
    const int c0 = blockIdx.y * 128;
    const int b  = blockIdx.z;

    const float* qb  = g_Qf + (size_t)b * Mm * Nn;
    const float* kvb = g_KV + (size_t)b * Mm * Cc;

    #pragma unroll
    for (int p = 0; p < 8; p++) {
        int idx = tid + p * 256;
        int row = idx >> 5;
        int c4  = (idx & 31) * 4;
        float4 q = *(const float4*)(qb + (size_t)row * Nn + n0 + c4);
        uint4 uq = { f2tf32(q.x), f2tf32(q.y), f2tf32(q.z), f2tf32(q.w) };
        *(uint4*)&Qs[row * OUT_STRIDE + c4] = uq;
        float4 kv = *(const float4*)(kvb + (size_t)row * Cc + c0 + c4);
        uint4 uk = { f2tf32(kv.x), f2tf32(kv.y), f2tf32(kv.z), f2tf32(kv.w) };
        *(uint4*)&KVs[row * OUT_STRIDE + c4] = uk;
    }
    __syncthreads();

    float acc[2][8][4];
    #pragma unroll
    for (int mi = 0; mi < 2; mi++)
        #pragma unroll
        for (int ni = 0; ni < 8; ni++)
            #pragma unroll
            for (int q = 0; q < 4; q++) acc[mi][ni][q] = 0.f;

    #pragma unroll
    for (int k8 = 0; k8 < 8; k8++) {
        const int kb = k8 * 8;
        uint32_t afr[2][4];
        #pragma unroll
        for (int mi = 0; mi < 2; mi++) {
            int cr = wm * 32 + mi * 16;
            afr[mi][0] = KVs[(kb + l4    ) * OUT_STRIDE + cr + g4];
            afr[mi][1] = KVs[(kb + l4    ) * OUT_STRIDE + cr + g4 + 8];
            afr[mi][2] = KVs[(kb + l4 + 4) * OUT_STRIDE + cr + g4];
            afr[mi][3] = KVs[(kb + l4 + 4) * OUT_STRIDE + cr + g4 + 8];
        }
        uint32_t bfr[8][2];
        #pragma unroll
        for (int ni = 0; ni < 8; ni++) {
            int nr = wn * 64 + ni * 8 + g4;
            bfr[ni][0] = Qs[(kb + l4    ) * OUT_STRIDE + nr];
            bfr[ni][1] = Qs[(kb + l4 + 4) * OUT_STRIDE + nr];
        }
        #pragma unroll
        for (int mi = 0; mi < 2; mi++)
            #pragma unroll
            for (int ni = 0; ni < 8; ni++)
                mma_tf32(acc[mi][ni], afr[mi], bfr[ni]);
    }

    const float g = gamma[0];
    float2 nrm[8];
    #pragma unroll
    for (int ni = 0; ni < 8; ni++)
        nrm[ni] = *(const float2*)(g_norm + b*Nn + n0 + wn*64 + ni*8 + l4*2);

    #pragma unroll
    for (int mi = 0; mi < 2; mi++) {
        #pragma unroll
        for (int h = 0; h < 2; h++) {
            const int c = c0 + wm * 32 + mi * 16 + h * 8 + g4;
            const size_t off = ((size_t)(b * Cc + c)) * Nn + n0;
            #pragma unroll
            for (int ni = 0; ni < 8; ni++) {
                int ncol = wn * 64 + ni * 8 + l4 * 2;
                float2 xv = *(const float2*)(x + off + ncol);
                float2 r;
                r.x = xv.x + g * nrm[ni].x * acc[mi][ni][h*2 + 0];
                r.y = xv.y + g * nrm[ni].y * acc[mi][ni][h*2 + 1];
                *(float2*)(out + off + ncol) = r;
            }
        }
    }
}

// ---------------- launch ----------------
extern "C" void kernel_launch(void* const* d_in, const int* in_sizes, int n_in,
                              void* d_out, int out_size) {
    const float* x     = (const float*)d_in[0];
    const float* wq    = (const float*)d_in[1];
    const float* bq    = (const float*)d_in[2];
    const float* wk    = (const float*)d_in[3];
    const float* bk    = (const float*)d_in[4];
    const float* wv    = (const float*)d_in[5];
    const float* bv    = (const float*)d_in[6];
    const float* gamma = (const float*)d_in[7];
    float* out = (float*)d_out;

    cudaFuncSetAttribute(out_mma_kernel, cudaFuncAttributeMaxDynamicSharedMemorySize, OUT_SMEM);

    zero_kernel<<<(Bz*Mm*Cc + 255) / 256, 256>>>();
    pack_kernel<<<(Rr*Cc + Rr + 255) / 256, 256>>>(wq, bq, wk, bk, wv, bv);
    transpose_kernel<<<dim3(Nn/64, Cc/64, Bz), 256>>>(x);
    gate_fin_kernel<<<(Bz*Cc + 255) / 256, 256>>>();
    qkv_mma_kernel<<<dim3(Nn/128, Rr/128, Bz), 256>>>();
    kv_mma_kernel<<<dim3(4, Cc/128, Bz), 256>>>();
    norm_kernel<<<Bz * Nn / 256, 256>>>();
    out_mma_kernel<<<dim3(Nn/128, Cc/128, Bz), 256, OUT_SMEM>>>(x, gamma, out);
}

// round 6
// speedup vs baseline: 5.6145x; 1.9714x over previous
#include <cuda_runtime.h>
#include <math.h>
#include <stdint.h>

#define Bz   8
#define Cc   512
#define Nn   4096
#define Mm   64
#define EPSc 1e-6f

// ---------------- device scratch ----------------
__device__ float g_Qf[Bz*Mm*Nn];   // softplus(Q)  [b][m][n]
__device__ float g_Kf[Bz*Mm*Nn];   // softplus(K)  [b][m][n]
__device__ float g_S [Bz*Mm*Cc];   // Kf . x^T     [b][m][c']
__device__ float g_KV[Bz*Mm*Cc];   // gated KV     [b][m][c]
__device__ float g_Ks2[Bz*Mm];     // sum_n Kf
__device__ float g_gmax[Bz*Cc];
__device__ float g_gsum[Bz*Cc];
__device__ float g_gate[Bz*Cc];

// ---------------- helpers ----------------
__device__ __forceinline__ uint32_t f2tf32(float f) {
    uint32_t r;
    asm("cvt.rna.tf32.f32 %0, %1;" : "=r"(r) : "f"(f));
    return r;
}
__device__ __forceinline__ void mma_tf32(float* d, const uint32_t* a, const uint32_t* b) {
    asm volatile(
        "mma.sync.aligned.m16n8k8.row.col.f32.tf32.tf32.f32 "
        "{%0,%1,%2,%3}, {%4,%5,%6,%7}, {%8,%9}, {%0,%1,%2,%3};"
        : "+f"(d[0]), "+f"(d[1]), "+f"(d[2]), "+f"(d[3])
        : "r"(a[0]), "r"(a[1]), "r"(a[2]), "r"(a[3]), "r"(b[0]), "r"(b[1]));
}
__device__ __forceinline__ void atomicMaxF(float* addr, float v) {
    if (v >= 0.f) atomicMax((int*)addr, __float_as_int(v));
    else          atomicMin((unsigned int*)addr, __float_as_uint(v));
}
__device__ __forceinline__ float softplus_f(float v) {
    return fmaxf(v, 0.f) + __logf(1.f + __expf(-fabsf(v)));
}

// ---------------- kernel: zero scratch ----------------
__global__ void zero_kernel() {
    int i = blockIdx.x * 256 + threadIdx.x;
    if (i < Bz*Mm*Cc) g_S[i] = 0.f;
    if (i < Bz*Mm) g_Ks2[i] = 0.f;
    if (i < Bz*Cc) { g_gmax[i] = -INFINITY; g_gsum[i] = 0.f; }
}

// ---------------- kernel: Q,K projection GEMM (tf32 mma) ----------------
// D[r][n] = sum_c W[r][c] * x[b][c][n], r in [0,128): rows 0..63 wq, 64..127 wk
// B operand loaded from x directly into natural [k][n] smem; transposed fragment gather.
__global__ __launch_bounds__(256, 2) void qk_mma_kernel(
    const float* __restrict__ x,
    const float* __restrict__ wq, const float* __restrict__ bq,
    const float* __restrict__ wk, const float* __restrict__ bk)
{
    __shared__ uint32_t As[128][36];   // [r][k]
    __shared__ uint32_t Xs[32][132];   // [k][n] natural

    const int tid = threadIdx.x;
    const int wid = tid >> 5;
    const int lid = tid & 31;
    const int g4  = lid >> 2;
    const int l4  = lid & 3;
    const int wm  = wid >> 1;          // 0..3 over r
    const int wn  = wid & 1;           // 0..1 over n

    const int n0 = blockIdx.x * 128;
    const int b  = blockIdx.y;

    const float* xb = x + (size_t)b * Cc * Nn;

    float acc[2][8][4];
    #pragma unroll
    for (int mi = 0; mi < 2; mi++)
        #pragma unroll
        for (int ni = 0; ni < 8; ni++)
            #pragma unroll
            for (int q = 0; q < 4; q++) acc[mi][ni][q] = 0.f;

    const int lrow = tid >> 3;          // 0..31
    const int lf   = (tid & 7) * 4;

    // B prefetch: idx-mapped, k = idx>>5, nf = (idx&31)*4
    float4 pb[4];
    #pragma unroll
    for (int p = 0; p < 4; p++) {
        int idx = tid + p * 256;
        pb[p] = *(const float4*)(xb + (size_t)(idx >> 5) * Nn + n0 + (idx & 31) * 4);
    }

    for (int kc = 0; kc < Cc; kc += 32) {
        if (kc) __syncthreads();
        // A: W rows (select wq/wk)
        #pragma unroll
        for (int p = 0; p < 4; p++) {
            int row = lrow + p * 32;
            const float* wsrc = (row < Mm) ? (wq + (size_t)row * Cc)
                                           : (wk + (size_t)(row - Mm) * Cc);
            float4 va = *(const float4*)(wsrc + kc + lf);
            uint4 ua = { f2tf32(va.x), f2tf32(va.y), f2tf32(va.z), f2tf32(va.w) };
            *(uint4*)&As[row][lf] = ua;
        }
        // B: x tile natural layout
        #pragma unroll
        for (int p = 0; p < 4; p++) {
            int idx = tid + p * 256;
            uint4 ub = { f2tf32(pb[p].x), f2tf32(pb[p].y), f2tf32(pb[p].z), f2tf32(pb[p].w) };
            *(uint4*)&Xs[idx >> 5][(idx & 31) * 4] = ub;
        }
        __syncthreads();
        if (kc + 32 < Cc) {
            #pragma unroll
            for (int p = 0; p < 4; p++) {
                int idx = tid + p * 256;
                pb[p] = *(const float4*)(xb + (size_t)(kc + 32 + (idx >> 5)) * Nn + n0 + (idx & 31) * 4);
            }
        }
        #pragma unroll
        for (int k8 = 0; k8 < 4; k8++) {
            const int kb = k8 * 8;
            uint32_t afr[2][4];
            #pragma unroll
            for (int mi = 0; mi < 2; mi++) {
                int mr = wm * 32 + mi * 16;
                afr[mi][0] = As[mr + g4    ][kb + l4];
                afr[mi][1] = As[mr + g4 + 8][kb + l4];
                afr[mi][2] = As[mr + g4    ][kb + l4 + 4];
                afr[mi][3] = As[mr + g4 + 8][kb + l4 + 4];
            }
            uint32_t bfr[8][2];
            #pragma unroll
            for (int ni = 0; ni < 8; ni++) {
                int nr = wn * 64 + ni * 8 + g4;
                bfr[ni][0] = Xs[kb + l4    ][nr];
                bfr[ni][1] = Xs[kb + l4 + 4][nr];
            }
            #pragma unroll
            for (int mi = 0; mi < 2; mi++)
                #pragma unroll
                for (int ni = 0; ni < 8; ni++)
                    mma_tf32(acc[mi][ni], afr[mi], bfr[ni]);
        }
    }

    // epilogue: bias + softplus; ksum for K rows
    #pragma unroll
    for (int mi = 0; mi < 2; mi++) {
        #pragma unroll
        for (int h = 0; h < 2; h++) {
            const int r = wm * 32 + mi * 16 + h * 8 + g4;
            float bias; float* dst; bool isK;
            if (r < Mm) { bias = bq[r];      dst = g_Qf + (size_t)(b*Mm + r) * Nn;      isK = false; }
            else        { bias = bk[r - Mm]; dst = g_Kf + (size_t)(b*Mm + r - Mm) * Nn; isK = true;  }
            float ks = 0.f;
            #pragma unroll
            for (int ni = 0; ni < 8; ni++) {
                float v0 = softplus_f(acc[mi][ni][h*2 + 0] + bias);
                float v1 = softplus_f(acc[mi][ni][h*2 + 1] + bias);
                if (isK) ks += v0 + v1;
                float2 w2 = { v0, v1 };
                *(float2*)(dst + n0 + wn * 64 + ni * 8 + l4 * 2) = w2;
            }
            if (isK) {
                ks += __shfl_xor_sync(0xffffffffu, ks, 1);
                ks += __shfl_xor_sync(0xffffffffu, ks, 2);
                if (l4 == 0) atomicAdd(&g_Ks2[b*Mm + (r - Mm)], ks);
            }
        }
    }
}

// ---------------- kernel: S = Kf . x^T (split-k over n) + fused gate partials ----------------
// S[b][m][c'] = sum_n Kf[b][m][n] * x[b][c'][n]
__global__ __launch_bounds__(256, 2) void s_mma_kernel(const float* __restrict__ x) {
    __shared__ uint32_t As[64][36];    // [m][k]
    __shared__ uint32_t Bs[128][36];   // [c'][k]

    const int tid = threadIdx.x;
    const int wid = tid >> 5;
    const int lid = tid & 31;
    const int g4  = lid >> 2;
    const int l4  = lid & 3;
    const int wm  = wid >> 2;          // 0..1
    const int wn  = wid & 3;           // 0..3

    const int b     = blockIdx.z;
    const int c0    = blockIdx.y * 128;
    const int nbase = blockIdx.x * 512;

    const float* kf = g_Kf + (size_t)b * Mm * Nn;
    const float* xp = x + ((size_t)(b*Cc + c0)) * Nn;

    float acc[2][4][4];
    #pragma unroll
    for (int mi = 0; mi < 2; mi++)
        #pragma unroll
        for (int ni = 0; ni < 4; ni++)
            #pragma unroll
            for (int q = 0; q < 4; q++) acc[mi][ni][q] = 0.f;

    float gmx[4] = {-INFINITY, -INFINITY, -INFINITY, -INFINITY};
    float gsm[4] = {0.f, 0.f, 0.f, 0.f};

    const int lrow = tid >> 3;
    const int lf   = (tid & 7) * 4;

    float4 pa[2], pb[4];
    #pragma unroll
    for (int p = 0; p < 2; p++)
        pa[p] = *(const float4*)(kf + (size_t)(lrow + p*32) * Nn + nbase + lf);
    #pragma unroll
    for (int p = 0; p < 4; p++)
        pb[p] = *(const float4*)(xp + (size_t)(lrow + p*32) * Nn + nbase + lf);

    for (int nc = 0; nc < 512; nc += 32) {
        if (nc) __syncthreads();
        #pragma unroll
        for (int p = 0; p < 2; p++) {
            uint4 ua = { f2tf32(pa[p].x), f2tf32(pa[p].y), f2tf32(pa[p].z), f2tf32(pa[p].w) };
            *(uint4*)&As[lrow + p*32][lf] = ua;
        }
        #pragma unroll
        for (int p = 0; p < 4; p++) {
            float4 v = pb[p];
            gmx[p] = fmaxf(gmx[p], fmaxf(fmaxf(v.x, v.y), fmaxf(v.z, v.w)));
            gsm[p] += (v.x + v.y) + (v.z + v.w);
            uint4 ub = { f2tf32(v.x), f2tf32(v.y), f2tf32(v.z), f2tf32(v.w) };
            *(uint4*)&Bs[lrow + p*32][lf] = ub;
        }
        __syncthreads();
        if (nc + 32 < 512) {
            int n = nbase + nc + 32;
            #pragma unroll
            for (int p = 0; p < 2; p++)
                pa[p] = *(const float4*)(kf + (size_t)(lrow + p*32) * Nn + n + lf);
            #pragma unroll
            for (int p = 0; p < 4; p++)
                pb[p] = *(const float4*)(xp + (size_t)(lrow + p*32) * Nn + n + lf);
        }
        #pragma unroll
        for (int k8 = 0; k8 < 4; k8++) {
            const int kb = k8 * 8;
            uint32_t afr[2][4];
            #pragma unroll
            for (int mi = 0; mi < 2; mi++) {
                int mr = wm * 32 + mi * 16;
                afr[mi][0] = As[mr + g4    ][kb + l4];
                afr[mi][1] = As[mr + g4 + 8][kb + l4];
                afr[mi][2] = As[mr + g4    ][kb + l4 + 4];
                afr[mi][3] = As[mr + g4 + 8][kb + l4 + 4];
            }
            uint32_t bfr[4][2];
            #pragma unroll
            for (int ni = 0; ni < 4; ni++) {
                int nr = wn * 32 + ni * 8 + g4;
                bfr[ni][0] = Bs[nr][kb + l4];
                bfr[ni][1] = Bs[nr][kb + l4 + 4];
            }
            #pragma unroll
            for (int mi = 0; mi < 2; mi++)
                #pragma unroll
                for (int ni = 0; ni < 4; ni++)
                    mma_tf32(acc[mi][ni], afr[mi], bfr[ni]);
        }
    }

    // gate partials: reduce across the 8 lanes sharing each loaded row
    #pragma unroll
    for (int p = 0; p < 4; p++) {
        float mx = gmx[p], sm = gsm[p];
        #pragma unroll
        for (int o = 1; o < 8; o <<= 1) {
            mx = fmaxf(mx, __shfl_xor_sync(0xffffffffu, mx, o));
            sm += __shfl_xor_sync(0xffffffffu, sm, o);
        }
        if ((lid & 7) == 0) {
            int c = c0 + lrow + p * 32;
            atomicMaxF(&g_gmax[b*Cc + c], mx);
            atomicAdd(&g_gsum[b*Cc + c], sm);
        }
    }

    // accumulate S
    #pragma unroll
    for (int mi = 0; mi < 2; mi++) {
        #pragma unroll
        for (int h = 0; h < 2; h++) {
            const int m = wm * 32 + mi * 16 + h * 8 + g4;
            float* srow = g_S + (size_t)(b*Mm + m) * Cc + c0;
            #pragma unroll
            for (int ni = 0; ni < 4; ni++) {
                int c = wn * 32 + ni * 8 + l4 * 2;
                atomicAdd(srow + c,     acc[mi][ni][h*2 + 0]);
                atomicAdd(srow + c + 1, acc[mi][ni][h*2 + 1]);
            }
        }
    }
}

// ---------------- kernel: finalize gate ----------------
__global__ void gate_fin_kernel() {
    int i = blockIdx.x * 256 + threadIdx.x;
    if (i < Bz*Cc) g_gate[i] = g_gmax[i] + g_gsum[i] * (1.f / Nn);
}

// ---------------- kernel: KV = gate * (S . Wv^T + Ks2 (x) bv)  [tf32 mma, k=512] ----------------
__global__ __launch_bounds__(256) void kv2_kernel(const float* __restrict__ wv,
                                                  const float* __restrict__ bv) {
    __shared__ uint32_t As[64][36];    // [m][k=c']
    __shared__ uint32_t Bs[64][36];    // [c][k=c']

    const int tid = threadIdx.x;
    const int wid = tid >> 5;
    const int lid = tid & 31;
    const int g4  = lid >> 2;
    const int l4  = lid & 3;
    const int wm  = wid >> 2;          // 0..1
    const int wn  = wid & 3;           // 0..3

    const int c0 = blockIdx.x * 64;
    const int b  = blockIdx.y;

    const float* sp  = g_S + (size_t)b * Mm * Cc;
    const float* wvp = wv + (size_t)c0 * Cc;

    float acc[2][2][4];
    #pragma unroll
    for (int mi = 0; mi < 2; mi++)
        #pragma unroll
        for (int ni = 0; ni < 2; ni++)
            #pragma unroll
            for (int q = 0; q < 4; q++) acc[mi][ni][q] = 0.f;

    for (int kc = 0; kc < Cc; kc += 32) {
        if (kc) __syncthreads();
        #pragma unroll
        for (int p = 0; p < 2; p++) {
            int idx = tid + p * 256;
            int row = idx >> 3;
            int lf  = (idx & 7) * 4;
            float4 va = *(const float4*)(sp + (size_t)row * Cc + kc + lf);
            uint4 ua = { f2tf32(va.x), f2tf32(va.y), f2tf32(va.z), f2tf32(va.w) };
            *(uint4*)&As[row][lf] = ua;
            float4 vb = *(const float4*)(wvp + (size_t)row * Cc + kc + lf);
            uint4 ub = { f2tf32(vb.x), f2tf32(vb.y), f2tf32(vb.z), f2tf32(vb.w) };
            *(uint4*)&Bs[row][lf] = ub;
        }
        __syncthreads();
        #pragma unroll
        for (int k8 = 0; k8 < 4; k8++) {
            const int kb = k8 * 8;
            uint32_t afr[2][4];
            #pragma unroll
            for (int mi = 0; mi < 2; mi++) {
                int mr = wm * 32 + mi * 16;
                afr[mi][0] = As[mr + g4    ][kb + l4];
                afr[mi][1] = As[mr + g4 + 8][kb + l4];
                afr[mi][2] = As[mr + g4    ][kb + l4 + 4];
                afr[mi][3] = As[mr + g4 + 8][kb + l4 + 4];
            }
            uint32_t bfr[2][2];
            #pragma unroll
            for (int ni = 0; ni < 2; ni++) {
                int nr = wn * 16 + ni * 8 + g4;
                bfr[ni][0] = Bs[nr][kb + l4];
                bfr[ni][1] = Bs[nr][kb + l4 + 4];
            }
            #pragma unroll
            for (int mi = 0; mi < 2; mi++)
                #pragma unroll
                for (int ni = 0; ni < 2; ni++)
                    mma_tf32(acc[mi][ni], afr[mi], bfr[ni]);
        }
    }

    #pragma unroll
    for (int mi = 0; mi < 2; mi++) {
        #pragma unroll
        for (int h = 0; h < 2; h++) {
            const int m = wm * 32 + mi * 16 + h * 8 + g4;
            const float ksm = g_Ks2[b*Mm + m];
            float* kvrow = g_KV + (size_t)(b*Mm + m) * Cc;
            #pragma unroll
            for (int ni = 0; ni < 2; ni++) {
                int c = c0 + wn * 16 + ni * 8 + l4 * 2;
                float v0 = g_gate[b*Cc + c]     * (acc[mi][ni][h*2 + 0] + ksm * bv[c]);
                float v1 = g_gate[b*Cc + c + 1] * (acc[mi][ni][h*2 + 1] + ksm * bv[c + 1]);
                float2 w2 = { v0, v1 };
                *(float2*)(kvrow + c) = w2;
            }
        }
    }
}

// ---------------- kernel: out = x + gamma * norm * (KV^T @ Qf), norm fused in-block ----------------
#define OUT_STRIDE 136
#define OUT_SMEM ((2 * 64 * OUT_STRIDE + 128 + 64) * 4)
__global__ __launch_bounds__(256) void out_mma_kernel(const float* __restrict__ x,
                                                      const float* __restrict__ gamma,
                                                      float* __restrict__ out) {
    extern __shared__ uint32_t osm[];
    uint32_t* Qs  = osm;                        // [m][n]  64 x 136
    uint32_t* KVs = osm + 64 * OUT_STRIDE;      // [m][c]  64 x 136
    float* nrm_s  = (float*)(osm + 2 * 64 * OUT_STRIDE);   // [128]
    float* ks_s   = nrm_s + 128;                            // [64]

    const int tid = threadIdx.x;
    const int wid = tid >> 5;
    const int lid = tid & 31;
    const int g4  = lid >> 2;
    const int l4  = lid & 3;
    const int wm  = wid >> 1;          // 0..3  (c)
    const int wn  = wid & 1;           // 0..1  (n)

    const int n0 = blockIdx.x * 128;
    const int c0 = blockIdx.y * 128;
    const int b  = blockIdx.z;

    const float* qb  = g_Qf + (size_t)b * Mm * Nn;
    const float* kvb = g_KV + (size_t)b * Mm * Cc;

    #pragma unroll
    for (int p = 0; p < 8; p++) {
        int idx = tid + p * 256;
        int row = idx >> 5;
        int c4  = (idx & 31) * 4;
        float4 q = *(const float4*)(qb + (size_t)row * Nn + n0 + c4);
        uint4 uq = { f2tf32(q.x), f2tf32(q.y), f2tf32(q.z), f2tf32(q.w) };
        *(uint4*)&Qs[row * OUT_STRIDE + c4] = uq;
        float4 kv = *(const float4*)(kvb + (size_t)row * Cc + c0 + c4);
        uint4 uk = { f2tf32(kv.x), f2tf32(kv.y), f2tf32(kv.z), f2tf32(kv.w) };
        *(uint4*)&KVs[row * OUT_STRIDE + c4] = uk;
    }
    if (tid < 64) ks_s[tid] = g_Ks2[b*Mm + tid] + EPSc;
    __syncthreads();

    // in-block norm: 1 / sum_m Qf[m][n] * (Ks+EPS)
    if (tid < 128) {
        float s = 0.f;
        #pragma unroll
        for (int m = 0; m < Mm; m++)
            s = fmaf(__uint_as_float(Qs[m * OUT_STRIDE + tid]), ks_s[m], s);
        nrm_s[tid] = 1.f / s;
    }
    __syncthreads();

    float acc[2][8][4];
    #pragma unroll
    for (int mi = 0; mi < 2; mi++)
        #pragma unroll
        for (int ni = 0; ni < 8; ni++)
            #pragma unroll
            for (int q = 0; q < 4; q++) acc[mi][ni][q] = 0.f;

    #pragma unroll
    for (int k8 = 0; k8 < 8; k8++) {
        const int kb = k8 * 8;
        uint32_t afr[2][4];
        #pragma unroll
        for (int mi = 0; mi < 2; mi++) {
            int cr = wm * 32 + mi * 16;
            afr[mi][0] = KVs[(kb + l4    ) * OUT_STRIDE + cr + g4];
            afr[mi][1] = KVs[(kb + l4    ) * OUT_STRIDE + cr + g4 + 8];
            afr[mi][2] = KVs[(kb + l4 + 4) * OUT_STRIDE + cr + g4];
            afr[mi][3] = KVs[(kb + l4 + 4) * OUT_STRIDE + cr + g4 + 8];
        }
        uint32_t bfr[8][2];
        #pragma unroll
        for (int ni = 0; ni < 8; ni++) {
            int nr = wn * 64 + ni * 8 + g4;
            bfr[ni][0] = Qs[(kb + l4    ) * OUT_STRIDE + nr];
            bfr[ni][1] = Qs[(kb + l4 + 4) * OUT_STRIDE + nr];
        }
        #pragma unroll
        for (int mi = 0; mi < 2; mi++)
            #pragma unroll
            for (int ni = 0; ni < 8; ni++)
                mma_tf32(acc[mi][ni], afr[mi], bfr[ni]);
    }

    const float g = gamma[0];
    float2 nrm[8];
    #pragma unroll
    for (int ni = 0; ni < 8; ni++)
        nrm[ni] = *(float2*)&nrm_s[wn*64 + ni*8 + l4*2];

    #pragma unroll
    for (int mi = 0; mi < 2; mi++) {
        #pragma unroll
        for (int h = 0; h < 2; h++) {
            const int c = c0 + wm * 32 + mi * 16 + h * 8 + g4;
            const size_t off = ((size_t)(b * Cc + c)) * Nn + n0;
            #pragma unroll
            for (int ni = 0; ni < 8; ni++) {
                int ncol = wn * 64 + ni * 8 + l4 * 2;
                float2 xv = *(const float2*)(x + off + ncol);
                float2 r;
                r.x = xv.x + g * nrm[ni].x * acc[mi][ni][h*2 + 0];
                r.y = xv.y + g * nrm[ni].y * acc[mi][ni][h*2 + 1];
                *(float2*)(out + off + ncol) = r;
            }
        }
    }
}

// ---------------- launch ----------------
extern "C" void kernel_launch(void* const* d_in, const int* in_sizes, int n_in,
                              void* d_out, int out_size) {
    const float* x     = (const float*)d_in[0];
    const float* wq    = (const float*)d_in[1];
    const float* bq    = (const float*)d_in[2];
    const float* wk    = (const float*)d_in[3];
    const float* bk    = (const float*)d_in[4];
    const float* wv    = (const float*)d_in[5];
    const float* bv    = (const float*)d_in[6];
    const float* gamma = (const float*)d_in[7];
    float* out = (float*)d_out;

    cudaFuncSetAttribute(out_mma_kernel, cudaFuncAttributeMaxDynamicSharedMemorySize, OUT_SMEM);

    zero_kernel<<<(Bz*Mm*Cc + 255) / 256, 256>>>();
    qk_mma_kernel<<<dim3(Nn/128, Bz), 256>>>(x, wq, bq, wk, bk);
    s_mma_kernel<<<dim3(8, Cc/128, Bz), 256>>>(x);
    gate_fin_kernel<<<(Bz*Cc + 255) / 256, 256>>>();
    kv2_kernel<<<dim3(Cc/64, Bz), 256>>>(wv, bv);
    out_mma_kernel<<<dim3(Nn/128, Cc/128, Bz), 256, OUT_SMEM>>>(x, gamma, out);
}